// round 15
// baseline (speedup 1.0000x reference)
#include <cuda_runtime.h>
#include <cuda_bf16.h>
#include <math.h>
#include <stdint.h>

// Problem constants
#define BATCH 8
#define SEQ   2048
#define HID   1024
#define WSIZE 64
#define NEG_INF (-1e9f)

// ---------------------------------------------------------------------------
// Device scratch
// ---------------------------------------------------------------------------
__device__ __nv_bfloat16 g_ah[BATCH * SEQ * HID];            // repr hi (32MB)
__device__ __nv_bfloat16 g_al[BATCH * SEQ * HID];            // repr lo (32MB)
__device__ __nv_bfloat16 g_qh[BATCH * SEQ * HID];            // Q' hi   (32MB)
__device__ __nv_bfloat16 g_ql[BATCH * SEQ * HID];            // Q' lo   (32MB)
__device__ __nv_bfloat16 g_bh[HID * HID];                    // W^T hi  (2MB)
__device__ __nv_bfloat16 g_bl[HID * HID];                    // W^T lo  (2MB)

// ---------------------------------------------------------------------------
// Host-side pipeline resources (created once at module load; host objects
// only — no device memory). Every kernel_launch call records identical work.
// ---------------------------------------------------------------------------
static cudaStream_t g_s2;
static cudaEvent_t  g_evG[4];   // GEMM stage done
static cudaEvent_t  g_evA;      // attn chain done
struct PipeInit {
    PipeInit() {
        cudaStreamCreateWithFlags(&g_s2, cudaStreamNonBlocking);
        for (int i = 0; i < 4; i++)
            cudaEventCreateWithFlags(&g_evG[i], cudaEventDisableTiming);
        cudaEventCreateWithFlags(&g_evA, cudaEventDisableTiming);
    }
};
static PipeInit g_pipe_init;

// ---------------------------------------------------------------------------
// Helpers
// ---------------------------------------------------------------------------
__device__ __forceinline__ uint32_t smem_u32(const void* p) {
    uint32_t a;
    asm("{ .reg .u64 t; cvta.to.shared.u64 t, %1; cvt.u32.u64 %0, t; }"
        : "=r"(a) : "l"(p));
    return a;
}
__device__ __forceinline__ void cp16(uint32_t dst, const void* src) {
    asm volatile("cp.async.cg.shared.global [%0], [%1], 16;\n" :: "r"(dst), "l"(src));
}
#define CP_COMMIT() asm volatile("cp.async.commit_group;\n" ::: "memory")
#define CP_WAIT(n)  asm volatile("cp.async.wait_group %0;\n" :: "n"(n) : "memory")

__device__ __forceinline__ void ldsm_x4(uint32_t addr, uint32_t* r) {
    asm volatile("ldmatrix.sync.aligned.m8n8.x4.shared.b16 {%0,%1,%2,%3}, [%4];"
                 : "=r"(r[0]), "=r"(r[1]), "=r"(r[2]), "=r"(r[3]) : "r"(addr));
}
__device__ __forceinline__ void ldsm_x4_t(uint32_t addr, uint32_t* r) {
    asm volatile("ldmatrix.sync.aligned.m8n8.x4.trans.shared.b16 {%0,%1,%2,%3}, [%4];"
                 : "=r"(r[0]), "=r"(r[1]), "=r"(r[2]), "=r"(r[3]) : "r"(addr));
}
__device__ __forceinline__ void mma_bf16(float* d, const uint32_t* a, const uint32_t* b) {
    asm volatile("mma.sync.aligned.m16n8k16.row.col.f32.bf16.bf16.f32 "
                 "{%0,%1,%2,%3}, {%4,%5,%6,%7}, {%8,%9}, {%0,%1,%2,%3};"
                 : "+f"(d[0]), "+f"(d[1]), "+f"(d[2]), "+f"(d[3])
                 : "r"(a[0]), "r"(a[1]), "r"(a[2]), "r"(a[3]),
                   "r"(b[0]), "r"(b[1]));
}
__device__ __forceinline__ void zero16(uint32_t dst) {
    asm volatile("st.shared.v4.b32 [%0], {%1,%1,%1,%1};" :: "r"(dst), "r"(0u) : "memory");
}

// ---------------------------------------------------------------------------
// Split kernels
// ---------------------------------------------------------------------------
__global__ __launch_bounds__(256)
void split_repr_kernel(const float* __restrict__ x,
                       __nv_bfloat16* __restrict__ hi,
                       __nv_bfloat16* __restrict__ lo)
{
    int i = (blockIdx.x * 256 + threadIdx.x) * 4;
    float4 v = *(const float4*)(x + i);
    __nv_bfloat16 h0 = __float2bfloat16_rn(v.x);
    __nv_bfloat16 h1 = __float2bfloat16_rn(v.y);
    __nv_bfloat16 h2 = __float2bfloat16_rn(v.z);
    __nv_bfloat16 h3 = __float2bfloat16_rn(v.w);
    __nv_bfloat16 l0 = __float2bfloat16_rn(v.x - __bfloat162float(h0));
    __nv_bfloat16 l1 = __float2bfloat16_rn(v.y - __bfloat162float(h1));
    __nv_bfloat16 l2 = __float2bfloat16_rn(v.z - __bfloat162float(h2));
    __nv_bfloat16 l3 = __float2bfloat16_rn(v.w - __bfloat162float(h3));
    __nv_bfloat162 hp0 = __nv_bfloat162(h0, h1), hp1 = __nv_bfloat162(h2, h3);
    __nv_bfloat162 lp0 = __nv_bfloat162(l0, l1), lp1 = __nv_bfloat162(l2, l3);
    *(uint2*)(hi + i) = make_uint2(*(uint32_t*)&hp0, *(uint32_t*)&hp1);
    *(uint2*)(lo + i) = make_uint2(*(uint32_t*)&lp0, *(uint32_t*)&lp1);
}

// W^T split via 32x32 smem-tiled transpose: bh/bl[n][k] = split(W[k][n])
__global__ __launch_bounds__(256)
void wsplit_kernel(const float* __restrict__ W,
                   __nv_bfloat16* __restrict__ bh,
                   __nv_bfloat16* __restrict__ bl)
{
    __shared__ float t[32][33];
    const int tx  = threadIdx.x & 31;
    const int ty0 = threadIdx.x >> 5;
    const int bc  = (blockIdx.x & 31) * 32;
    const int br  = (blockIdx.x >> 5) * 32;

#pragma unroll
    for (int i = 0; i < 4; i++) {
        int r = ty0 + i * 8;
        t[r][tx] = W[(size_t)(br + r) * HID + bc + tx];
    }
    __syncthreads();
#pragma unroll
    for (int i = 0; i < 4; i++) {
        int rn = ty0 + i * 8;
        float x = t[tx][rn];
        __nv_bfloat16 h = __float2bfloat16_rn(x);
        __nv_bfloat16 l = __float2bfloat16_rn(x - __bfloat162float(h));
        size_t idx = (size_t)(bc + rn) * HID + br + tx;
        bh[idx] = h; bl[idx] = l;
    }
}

// ---------------------------------------------------------------------------
// HMMA split-bf16 GEMM (2 CTA/SM; single-sync pipeline); grid.y covers the
// M-tiles of a 2-batch slice; mbase = first M-tile of the slice.
// ---------------------------------------------------------------------------
#define GBM 128
#define GBN 128
#define GBK 32
#define ROWB 80
#define GS_AH 0
#define GS_AL (128 * ROWB)
#define GS_BH (2 * 128 * ROWB)
#define GS_BL (3 * 128 * ROWB)
#define GS_SZ (4 * 128 * ROWB)

__global__ __launch_bounds__(256, 2)
void gemm_hmma_kernel(const __nv_bfloat16* __restrict__ Ah,
                      const __nv_bfloat16* __restrict__ Al,
                      const __nv_bfloat16* __restrict__ Bh,
                      const __nv_bfloat16* __restrict__ Bl,
                      __nv_bfloat16* __restrict__ Qh,
                      __nv_bfloat16* __restrict__ Ql,
                      int mbase)
{
    extern __shared__ char dynsm[];
    const uint32_t sbase = smem_u32(dynsm);
    const int tid   = threadIdx.x;
    const int wid   = tid >> 5;
    const int lane  = tid & 31;
    const int warpM = wid >> 1;
    const int warpN = wid & 1;

    const int rowA = (mbase + blockIdx.y) * GBM;
    const int colB = blockIdx.x * GBN;

    float acc[2][8][4];
#pragma unroll
    for (int mt = 0; mt < 2; mt++)
#pragma unroll
        for (int nt = 0; nt < 8; nt++)
#pragma unroll
            for (int q = 0; q < 4; q++) acc[mt][nt][q] = 0.f;

    auto load_stage = [&](int c, int stage) {
        const int k0 = c * GBK;
        const uint32_t tb = sbase + stage * GS_SZ;
#pragma unroll
        for (int i = 0; i < 2; i++) {
            int e = tid + i * 256;
            int r = e >> 2, cc = e & 3;
            uint32_t d = (uint32_t)(r * ROWB + cc * 16);
            cp16(tb + GS_AH + d, Ah + (size_t)(rowA + r) * HID + k0 + cc * 8);
            cp16(tb + GS_AL + d, Al + (size_t)(rowA + r) * HID + k0 + cc * 8);
            cp16(tb + GS_BH + d, Bh + (size_t)(colB + r) * HID + k0 + cc * 8);
            cp16(tb + GS_BL + d, Bl + (size_t)(colB + r) * HID + k0 + cc * 8);
        }
        CP_COMMIT();
    };

    load_stage(0, 0);

    const int NK = HID / GBK;
    for (int c = 0; c < NK; c++) {
        CP_WAIT(0);
        __syncthreads();
        if (c + 1 < NK) load_stage(c + 1, (c + 1) & 1);

        const uint32_t tb = sbase + (c & 1) * GS_SZ;
        const uint32_t a_l = (uint32_t)((warpM * 32 + (lane & 15)) * ROWB + (lane >> 4) * 16);
        const int g = lane >> 3;
        const uint32_t b_l = (uint32_t)((warpN * 64 + ((g >> 1) << 3) + (lane & 7)) * ROWB + (g & 1) * 16);

#pragma unroll
        for (int kk = 0; kk < 2; kk++) {
            const uint32_t ko = (uint32_t)(kk * 32);
            uint32_t ah[2][4], al[2][4], bhf[8][2], blf[8][2];
#pragma unroll
            for (int mt = 0; mt < 2; mt++) {
                uint32_t off = a_l + (uint32_t)(mt * 16 * ROWB) + ko;
                ldsm_x4(tb + GS_AH + off, ah[mt]);
                ldsm_x4(tb + GS_AL + off, al[mt]);
            }
#pragma unroll
            for (int np = 0; np < 4; np++) {
                uint32_t off = b_l + (uint32_t)(np * 16 * ROWB) + ko;
                uint32_t r[4];
                ldsm_x4(tb + GS_BH + off, r);
                bhf[2 * np][0] = r[0]; bhf[2 * np][1] = r[1];
                bhf[2 * np + 1][0] = r[2]; bhf[2 * np + 1][1] = r[3];
                ldsm_x4(tb + GS_BL + off, r);
                blf[2 * np][0] = r[0]; blf[2 * np][1] = r[1];
                blf[2 * np + 1][0] = r[2]; blf[2 * np + 1][1] = r[3];
            }
#pragma unroll
            for (int mt = 0; mt < 2; mt++) {
#pragma unroll
                for (int nt = 0; nt < 8; nt++) {
                    mma_bf16(acc[mt][nt], ah[mt], bhf[nt]);
                    mma_bf16(acc[mt][nt], ah[mt], blf[nt]);
                    mma_bf16(acc[mt][nt], al[mt], bhf[nt]);
                }
            }
        }
    }

    const int r0 = rowA + warpM * 32 + (lane >> 2);
    const int c0 = colB + warpN * 64 + (lane & 3) * 2;
#pragma unroll
    for (int mt = 0; mt < 2; mt++) {
#pragma unroll
        for (int nt = 0; nt < 8; nt++) {
            int rr = r0 + mt * 16;
            int cc = c0 + nt * 8;
#pragma unroll
            for (int h = 0; h < 2; h++) {
                float a = acc[mt][nt][2 * h + 0];
                float b = acc[mt][nt][2 * h + 1];
                size_t idx = (size_t)(rr + 8 * h) * HID + cc;
                __nv_bfloat16 ha = __float2bfloat16_rn(a);
                __nv_bfloat16 hb = __float2bfloat16_rn(b);
                __nv_bfloat16 la = __float2bfloat16_rn(a - __bfloat162float(ha));
                __nv_bfloat16 lb = __float2bfloat16_rn(b - __bfloat162float(hb));
                __nv_bfloat162 hp(ha, hb), lp(la, lb);
                *(uint32_t*)(Qh + idx) = *(uint32_t*)&hp;
                *(uint32_t*)(Ql + idx) = *(uint32_t*)&lp;
            }
        }
    }
}

// ---------------------------------------------------------------------------
// Banded attention — EXACT R10 body; grid.y covers 2 batches via bbase.
// ---------------------------------------------------------------------------
#define TQ 64
#define TK 192
#define SW2 200
#define PSTR 216

#define A3_QSTG 40960
#define A3_S    0
#define A3_PH   55296
#define A3_PL   82944
#define A3_V    0
#define A3_SMEM 110592

__global__ __launch_bounds__(256, 2)
void attn_hmma_kernel(const __nv_bfloat16* __restrict__ Qh,
                      const __nv_bfloat16* __restrict__ Ql,
                      const __nv_bfloat16* __restrict__ Kh,
                      const __nv_bfloat16* __restrict__ Kl,
                      const float* __restrict__ repr,
                      float* __restrict__ out,
                      int bbase)
{
    extern __shared__ char dynsm[];
    const uint32_t sbase = smem_u32(dynsm);
    float* S = (float*)(dynsm + A3_S);

    const int b   = bbase + blockIdx.y;
    const int q0  = blockIdx.x * TQ;
    const int k0  = q0 - WSIZE;
    const int tid = threadIdx.x;
    const int wid = tid >> 5;
    const int lane = tid & 31;
    const int warpM = wid >> 2;
    const int warpN = wid & 3;

    const size_t bOfs = (size_t)b * SEQ * HID;
    const float* reB = repr + bOfs;
    float*       oB  = out  + bOfs;

    // ---------------- Phase 1: S = Q' K^T (split bf16 HMMA) ---------------
    {
        auto load_qk = [&](int c, int stage) {
            const int ko = c * 32;
            const uint32_t tb = sbase + stage * A3_QSTG;
            {
                int r = tid >> 2, cc = tid & 3;
                uint32_t d = (uint32_t)(r * 80 + cc * 16);
                cp16(tb + 0    + d, Qh + bOfs + (size_t)(q0 + r) * HID + ko + cc * 8);
                cp16(tb + 5120 + d, Ql + bOfs + (size_t)(q0 + r) * HID + ko + cc * 8);
            }
#pragma unroll
            for (int i = 0; i < 3; i++) {
                int e = tid + i * 256;
                int r = e >> 2, cc = e & 3;
                int j = k0 + r;
                uint32_t d = (uint32_t)(r * 80 + cc * 16);
                if (j >= 0 && j < SEQ) {
                    cp16(tb + 10240 + d, Kh + bOfs + (size_t)j * HID + ko + cc * 8);
                    cp16(tb + 25600 + d, Kl + bOfs + (size_t)j * HID + ko + cc * 8);
                } else {
                    zero16(tb + 10240 + d);
                    zero16(tb + 25600 + d);
                }
            }
            CP_COMMIT();
        };

        float acc[2][6][4];
#pragma unroll
        for (int mt = 0; mt < 2; mt++)
#pragma unroll
            for (int nt = 0; nt < 6; nt++)
#pragma unroll
                for (int q = 0; q < 4; q++) acc[mt][nt][q] = 0.f;

        load_qk(0, 0);
        for (int c = 0; c < 32; c++) {
            if (c + 1 < 32) { load_qk(c + 1, (c + 1) & 1); CP_WAIT(1); }
            else            { CP_WAIT(0); }
            __syncthreads();

            const uint32_t tb = sbase + (c & 1) * A3_QSTG;
            const uint32_t a_l = (uint32_t)((warpM * 32 + (lane & 15)) * 80 + (lane >> 4) * 16);
            const int g = lane >> 3;
            const uint32_t b_l = (uint32_t)((warpN * 48 + ((g >> 1) << 3) + (lane & 7)) * 80 + (g & 1) * 16);

#pragma unroll
            for (int kk = 0; kk < 2; kk++) {
                const uint32_t ko = (uint32_t)(kk * 32);
                uint32_t aqh[2][4], aql[2][4], bkh[6][2], bkl[6][2];
#pragma unroll
                for (int mt = 0; mt < 2; mt++) {
                    uint32_t off = a_l + (uint32_t)(mt * 16 * 80) + ko;
                    ldsm_x4(tb + 0    + off, aqh[mt]);
                    ldsm_x4(tb + 5120 + off, aql[mt]);
                }
#pragma unroll
                for (int np = 0; np < 3; np++) {
                    uint32_t off = b_l + (uint32_t)(np * 16 * 80) + ko;
                    uint32_t r[4];
                    ldsm_x4(tb + 10240 + off, r);
                    bkh[2 * np][0] = r[0]; bkh[2 * np][1] = r[1];
                    bkh[2 * np + 1][0] = r[2]; bkh[2 * np + 1][1] = r[3];
                    ldsm_x4(tb + 25600 + off, r);
                    bkl[2 * np][0] = r[0]; bkl[2 * np][1] = r[1];
                    bkl[2 * np + 1][0] = r[2]; bkl[2 * np + 1][1] = r[3];
                }
#pragma unroll
                for (int mt = 0; mt < 2; mt++)
#pragma unroll
                    for (int nt = 0; nt < 6; nt++) {
                        mma_bf16(acc[mt][nt], aqh[mt], bkh[nt]);
                        mma_bf16(acc[mt][nt], aqh[mt], bkl[nt]);
                        mma_bf16(acc[mt][nt], aql[mt], bkh[nt]);
                    }
            }
            __syncthreads();
        }

        __syncthreads();

        const int r0 = warpM * 32 + (lane >> 2);
        const int c0 = warpN * 48 + (lane & 3) * 2;
#pragma unroll
        for (int mt = 0; mt < 2; mt++)
#pragma unroll
            for (int nt = 0; nt < 6; nt++) {
                *(float2*)&S[(r0 + mt * 16) * SW2 + c0 + nt * 8] =
                    make_float2(acc[mt][nt][0], acc[mt][nt][1]);
                *(float2*)&S[(r0 + mt * 16 + 8) * SW2 + c0 + nt * 8] =
                    make_float2(acc[mt][nt][2], acc[mt][nt][3]);
            }
        __syncthreads();
    }

    // ---------------- Phase 2: masked softmax + P split to bf16 ------------
    {
        __nv_bfloat16* ph = (__nv_bfloat16*)(dynsm + A3_PH);
        __nv_bfloat16* pl = (__nv_bfloat16*)(dynsm + A3_PL);
        const int row  = tid >> 2;
        const int quad = tid & 3;
        const int cbeg = quad * 48;
        const int i_gl = q0 + row;

        float mx = -3.4e38f;
#pragma unroll 8
        for (int c = cbeg; c < cbeg + 48; c++) {
            int j = k0 + c;
            int d = i_gl - j;
            bool valid = (j >= 0) && (j < SEQ) && (d <= WSIZE) && (d >= -WSIZE);
            float v = valid ? S[row * SW2 + c] : NEG_INF;
            S[row * SW2 + c] = v;
            mx = fmaxf(mx, v);
        }
        mx = fmaxf(mx, __shfl_xor_sync(0xffffffffu, mx, 1));
        mx = fmaxf(mx, __shfl_xor_sync(0xffffffffu, mx, 2));

        float sum = 0.f;
#pragma unroll 8
        for (int c = cbeg; c < cbeg + 48; c++) {
            float e = __expf(S[row * SW2 + c] - mx);
            S[row * SW2 + c] = e;
            sum += e;
        }
        sum += __shfl_xor_sync(0xffffffffu, sum, 1);
        sum += __shfl_xor_sync(0xffffffffu, sum, 2);
        float inv = 1.f / sum;
#pragma unroll 8
        for (int c = cbeg; c < cbeg + 48; c++) {
            float p = S[row * SW2 + c] * inv;
            __nv_bfloat16 hp = __float2bfloat16_rn(p);
            __nv_bfloat16 lp = __float2bfloat16_rn(p - __bfloat162float(hp));
            ph[row * PSTR + c] = hp;
            pl[row * PSTR + c] = lp;
        }
    }
    __syncthreads();

    // ---------------- Phase 3: out = repr + relu(P @ V), band-aware --------
    {
        auto load_v = [&](int ch) {
            const int d0 = ch * 64;
            const uint32_t tb = sbase + A3_V;
#pragma unroll
            for (int i = 0; i < 6; i++) {
                int e = tid + i * 256;
                int r = e >> 3, cc = e & 7;
                int j = k0 + r;
                uint32_t d = (uint32_t)(r * 144 + cc * 16);
                if (j >= 0 && j < SEQ) {
                    cp16(tb + d,         Kh + bOfs + (size_t)j * HID + d0 + cc * 8);
                    cp16(tb + 27648 + d, Kl + bOfs + (size_t)j * HID + d0 + cc * 8);
                } else {
                    zero16(tb + d);
                    zero16(tb + 27648 + d);
                }
            }
            CP_COMMIT();
        };

        const uint32_t a_l = (uint32_t)((warpM * 32 + (lane & 15)) * (PSTR * 2) + (lane >> 4) * 16);
        const int g = lane >> 3;
        const int base0 = warpM * 2;

        for (int ch = 0; ch < 16; ch++) {
            load_v(ch);
            CP_WAIT(0);
            __syncthreads();

            const uint32_t vb = sbase + A3_V;
            float acc[2][2][4];
#pragma unroll
            for (int mt = 0; mt < 2; mt++)
#pragma unroll
                for (int nt = 0; nt < 2; nt++)
#pragma unroll
                    for (int q = 0; q < 4; q++) acc[mt][nt][q] = 0.f;

#pragma unroll
            for (int kq = 0; kq < 10; kq++) {
                const int ks = base0 + kq;
                uint32_t vaddr = (uint32_t)((ks * 16 + (g & 1) * 8 + (lane & 7)) * 144
                                            + (warpN * 16 + (g >> 1) * 8) * 2);
                uint32_t bvh[4], bvl[4];
                ldsm_x4_t(vb + vaddr, bvh);
                ldsm_x4_t(vb + 27648 + vaddr, bvl);

                if (kq < 9) {
                    uint32_t aph[4], apl[4];
                    uint32_t off = a_l + (uint32_t)(ks * 32);
                    ldsm_x4(sbase + A3_PH + off, aph);
                    ldsm_x4(sbase + A3_PL + off, apl);
#pragma unroll
                    for (int nt = 0; nt < 2; nt++) {
                        mma_bf16(acc[0][nt], aph, &bvh[nt * 2]);
                        mma_bf16(acc[0][nt], aph, &bvl[nt * 2]);
                        mma_bf16(acc[0][nt], apl, &bvh[nt * 2]);
                    }
                }
                if (kq > 0) {
                    uint32_t aph[4], apl[4];
                    uint32_t off = a_l + (uint32_t)(16 * (PSTR * 2)) + (uint32_t)(ks * 32);
                    ldsm_x4(sbase + A3_PH + off, aph);
                    ldsm_x4(sbase + A3_PL + off, apl);
#pragma unroll
                    for (int nt = 0; nt < 2; nt++) {
                        mma_bf16(acc[1][nt], aph, &bvh[nt * 2]);
                        mma_bf16(acc[1][nt], aph, &bvl[nt * 2]);
                        mma_bf16(acc[1][nt], apl, &bvh[nt * 2]);
                    }
                }
            }

            const int rq = q0 + warpM * 32 + (lane >> 2);
            const int cc0 = ch * 64 + warpN * 16 + (lane & 3) * 2;
#pragma unroll
            for (int mt = 0; mt < 2; mt++)
#pragma unroll
                for (int nt = 0; nt < 2; nt++) {
                    int rr = rq + mt * 16;
                    int cc = cc0 + nt * 8;
#pragma unroll
                    for (int h = 0; h < 2; h++) {
                        size_t idx = (size_t)(rr + 8 * h) * HID + cc;
                        float2 rv = *(const float2*)(reB + idx);
                        float2 ov = make_float2(rv.x + fmaxf(acc[mt][nt][2 * h], 0.f),
                                                rv.y + fmaxf(acc[mt][nt][2 * h + 1], 0.f));
                        *(float2*)(oB + idx) = ov;
                    }
                }
            __syncthreads();
        }
    }
}

// ---------------------------------------------------------------------------
// Launch: 4 GEMM stages (2 batches each) on default stream; attn stages on
// second stream gated by events -> attn(g) overlaps GEMM(g+1).
// ---------------------------------------------------------------------------
extern "C" void kernel_launch(void* const* d_in, const int* in_sizes, int n_in,
                              void* d_out, int out_size)
{
    const float* repr = (const float*)d_in[0];   // [8, 2048, 1024]
    const float* W    = (const float*)d_in[1];   // [1024, 1024]
    float* out        = (float*)d_out;

    __nv_bfloat16 *ah, *al, *qh, *ql, *bh, *bl;
    cudaGetSymbolAddress((void**)&ah, g_ah);
    cudaGetSymbolAddress((void**)&al, g_al);
    cudaGetSymbolAddress((void**)&qh, g_qh);
    cudaGetSymbolAddress((void**)&ql, g_ql);
    cudaGetSymbolAddress((void**)&bh, g_bh);
    cudaGetSymbolAddress((void**)&bl, g_bl);

    // 1) bf16 splits (default stream)
    split_repr_kernel<<<(BATCH * SEQ * HID) / (256 * 4), 256>>>(repr, ah, al);
    wsplit_kernel<<<(HID / 32) * (HID / 32), 256>>>(W, bh, bl);

    cudaFuncSetAttribute(gemm_hmma_kernel,
                         cudaFuncAttributeMaxDynamicSharedMemorySize, 2 * GS_SZ);
    cudaFuncSetAttribute(attn_hmma_kernel,
                         cudaFuncAttributeMaxDynamicSharedMemorySize, A3_SMEM);

    // 2) pipelined GEMM stages + overlapped attention
    for (int s = 0; s < 4; s++) {
        dim3 ggrid(HID / GBN, 32);                 // 8 x 32 = 256 CTAs (2 batches)
        gemm_hmma_kernel<<<ggrid, 256, 2 * GS_SZ>>>(ah, al, bh, bl, qh, ql, s * 32);
        cudaEventRecord(g_evG[s], 0);
        cudaStreamWaitEvent(g_s2, g_evG[s], 0);
        dim3 agrid(SEQ / TQ, 2);                   // 32 x 2 = 64 CTAs (2 batches)
        attn_hmma_kernel<<<agrid, 256, A3_SMEM, g_s2>>>(qh, ql, ah, al, repr, out, s * 2);
    }
    cudaEventRecord(g_evA, g_s2);
    cudaStreamWaitEvent(0, g_evA, 0);
}

// round 16
// speedup vs baseline: 1.2669x; 1.2669x over previous
#include <cuda_runtime.h>
#include <cuda_bf16.h>
#include <math.h>
#include <stdint.h>

// Problem constants
#define BATCH 8
#define SEQ   2048
#define HID   1024
#define WSIZE 64
#define NEG_INF (-1e9f)

// ---------------------------------------------------------------------------
// Device scratch
// ---------------------------------------------------------------------------
__device__ __nv_bfloat16 g_ah[BATCH * SEQ * HID];            // repr hi (32MB)
__device__ __nv_bfloat16 g_al[BATCH * SEQ * HID];            // repr lo (32MB)
__device__ __nv_bfloat16 g_qh[BATCH * SEQ * HID];            // Q' hi   (32MB)
__device__ __nv_bfloat16 g_ql[BATCH * SEQ * HID];            // Q' lo   (32MB)
__device__ __nv_bfloat16 g_bh[HID * HID];                    // W^T hi  (2MB)
__device__ __nv_bfloat16 g_bl[HID * HID];                    // W^T lo  (2MB)

// ---------------------------------------------------------------------------
// Helpers
// ---------------------------------------------------------------------------
__device__ __forceinline__ uint32_t smem_u32(const void* p) {
    uint32_t a;
    asm("{ .reg .u64 t; cvta.to.shared.u64 t, %1; cvt.u32.u64 %0, t; }"
        : "=r"(a) : "l"(p));
    return a;
}
__device__ __forceinline__ void cp16(uint32_t dst, const void* src) {
    asm volatile("cp.async.cg.shared.global [%0], [%1], 16;\n" :: "r"(dst), "l"(src));
}
#define CP_COMMIT() asm volatile("cp.async.commit_group;\n" ::: "memory")
#define CP_WAIT(n)  asm volatile("cp.async.wait_group %0;\n" :: "n"(n) : "memory")

__device__ __forceinline__ void ldsm_x4(uint32_t addr, uint32_t* r) {
    asm volatile("ldmatrix.sync.aligned.m8n8.x4.shared.b16 {%0,%1,%2,%3}, [%4];"
                 : "=r"(r[0]), "=r"(r[1]), "=r"(r[2]), "=r"(r[3]) : "r"(addr));
}
__device__ __forceinline__ void ldsm_x4_t(uint32_t addr, uint32_t* r) {
    asm volatile("ldmatrix.sync.aligned.m8n8.x4.trans.shared.b16 {%0,%1,%2,%3}, [%4];"
                 : "=r"(r[0]), "=r"(r[1]), "=r"(r[2]), "=r"(r[3]) : "r"(addr));
}
__device__ __forceinline__ void mma_bf16(float* d, const uint32_t* a, const uint32_t* b) {
    asm volatile("mma.sync.aligned.m16n8k16.row.col.f32.bf16.bf16.f32 "
                 "{%0,%1,%2,%3}, {%4,%5,%6,%7}, {%8,%9}, {%0,%1,%2,%3};"
                 : "+f"(d[0]), "+f"(d[1]), "+f"(d[2]), "+f"(d[3])
                 : "r"(a[0]), "r"(a[1]), "r"(a[2]), "r"(a[3]),
                   "r"(b[0]), "r"(b[1]));
}
__device__ __forceinline__ void zero16(uint32_t dst) {
    asm volatile("st.shared.v4.b32 [%0], {%1,%1,%1,%1};" :: "r"(dst), "r"(0u) : "memory");
}

// ---------------------------------------------------------------------------
// Split kernels
// ---------------------------------------------------------------------------
__global__ __launch_bounds__(256)
void split_repr_kernel(const float* __restrict__ x,
                       __nv_bfloat16* __restrict__ hi,
                       __nv_bfloat16* __restrict__ lo)
{
    int i = (blockIdx.x * 256 + threadIdx.x) * 4;
    float4 v = *(const float4*)(x + i);
    __nv_bfloat16 h0 = __float2bfloat16_rn(v.x);
    __nv_bfloat16 h1 = __float2bfloat16_rn(v.y);
    __nv_bfloat16 h2 = __float2bfloat16_rn(v.z);
    __nv_bfloat16 h3 = __float2bfloat16_rn(v.w);
    __nv_bfloat16 l0 = __float2bfloat16_rn(v.x - __bfloat162float(h0));
    __nv_bfloat16 l1 = __float2bfloat16_rn(v.y - __bfloat162float(h1));
    __nv_bfloat16 l2 = __float2bfloat16_rn(v.z - __bfloat162float(h2));
    __nv_bfloat16 l3 = __float2bfloat16_rn(v.w - __bfloat162float(h3));
    __nv_bfloat162 hp0 = __nv_bfloat162(h0, h1), hp1 = __nv_bfloat162(h2, h3);
    __nv_bfloat162 lp0 = __nv_bfloat162(l0, l1), lp1 = __nv_bfloat162(l2, l3);
    *(uint2*)(hi + i) = make_uint2(*(uint32_t*)&hp0, *(uint32_t*)&hp1);
    *(uint2*)(lo + i) = make_uint2(*(uint32_t*)&lp0, *(uint32_t*)&lp1);
}

// W^T split via 32x32 smem-tiled transpose: bh/bl[n][k] = split(W[k][n])
__global__ __launch_bounds__(256)
void wsplit_kernel(const float* __restrict__ W,
                   __nv_bfloat16* __restrict__ bh,
                   __nv_bfloat16* __restrict__ bl)
{
    __shared__ float t[32][33];
    const int tx  = threadIdx.x & 31;
    const int ty0 = threadIdx.x >> 5;
    const int bc  = (blockIdx.x & 31) * 32;
    const int br  = (blockIdx.x >> 5) * 32;

#pragma unroll
    for (int i = 0; i < 4; i++) {
        int r = ty0 + i * 8;
        t[r][tx] = W[(size_t)(br + r) * HID + bc + tx];
    }
    __syncthreads();
#pragma unroll
    for (int i = 0; i < 4; i++) {
        int rn = ty0 + i * 8;
        float x = t[tx][rn];
        __nv_bfloat16 h = __float2bfloat16_rn(x);
        __nv_bfloat16 l = __float2bfloat16_rn(x - __bfloat162float(h));
        size_t idx = (size_t)(bc + rn) * HID + br + tx;
        bh[idx] = h; bl[idx] = l;
    }
}

// ---------------------------------------------------------------------------
// HMMA split-bf16 GEMM: Q' = repr @ W (2 CTA/SM; single-sync pipeline)
// ---------------------------------------------------------------------------
#define GBM 128
#define GBN 128
#define GBK 32
#define ROWB 80
#define GS_AH 0
#define GS_AL (128 * ROWB)
#define GS_BH (2 * 128 * ROWB)
#define GS_BL (3 * 128 * ROWB)
#define GS_SZ (4 * 128 * ROWB)

__global__ __launch_bounds__(256, 2)
void gemm_hmma_kernel(const __nv_bfloat16* __restrict__ Ah,
                      const __nv_bfloat16* __restrict__ Al,
                      const __nv_bfloat16* __restrict__ Bh,
                      const __nv_bfloat16* __restrict__ Bl,
                      __nv_bfloat16* __restrict__ Qh,
                      __nv_bfloat16* __restrict__ Ql)
{
    extern __shared__ char dynsm[];
    const uint32_t sbase = smem_u32(dynsm);
    const int tid   = threadIdx.x;
    const int wid   = tid >> 5;
    const int lane  = tid & 31;
    const int warpM = wid >> 1;
    const int warpN = wid & 1;

    const int rowA = blockIdx.y * GBM;
    const int colB = blockIdx.x * GBN;

    float acc[2][8][4];
#pragma unroll
    for (int mt = 0; mt < 2; mt++)
#pragma unroll
        for (int nt = 0; nt < 8; nt++)
#pragma unroll
            for (int q = 0; q < 4; q++) acc[mt][nt][q] = 0.f;

    auto load_stage = [&](int c, int stage) {
        const int k0 = c * GBK;
        const uint32_t tb = sbase + stage * GS_SZ;
#pragma unroll
        for (int i = 0; i < 2; i++) {
            int e = tid + i * 256;
            int r = e >> 2, cc = e & 3;
            uint32_t d = (uint32_t)(r * ROWB + cc * 16);
            cp16(tb + GS_AH + d, Ah + (size_t)(rowA + r) * HID + k0 + cc * 8);
            cp16(tb + GS_AL + d, Al + (size_t)(rowA + r) * HID + k0 + cc * 8);
            cp16(tb + GS_BH + d, Bh + (size_t)(colB + r) * HID + k0 + cc * 8);
            cp16(tb + GS_BL + d, Bl + (size_t)(colB + r) * HID + k0 + cc * 8);
        }
        CP_COMMIT();
    };

    load_stage(0, 0);

    const int NK = HID / GBK;
    for (int c = 0; c < NK; c++) {
        CP_WAIT(0);
        __syncthreads();
        if (c + 1 < NK) load_stage(c + 1, (c + 1) & 1);

        const uint32_t tb = sbase + (c & 1) * GS_SZ;
        const uint32_t a_l = (uint32_t)((warpM * 32 + (lane & 15)) * ROWB + (lane >> 4) * 16);
        const int g = lane >> 3;
        const uint32_t b_l = (uint32_t)((warpN * 64 + ((g >> 1) << 3) + (lane & 7)) * ROWB + (g & 1) * 16);

#pragma unroll
        for (int kk = 0; kk < 2; kk++) {
            const uint32_t ko = (uint32_t)(kk * 32);
            uint32_t ah[2][4], al[2][4], bhf[8][2], blf[8][2];
#pragma unroll
            for (int mt = 0; mt < 2; mt++) {
                uint32_t off = a_l + (uint32_t)(mt * 16 * ROWB) + ko;
                ldsm_x4(tb + GS_AH + off, ah[mt]);
                ldsm_x4(tb + GS_AL + off, al[mt]);
            }
#pragma unroll
            for (int np = 0; np < 4; np++) {
                uint32_t off = b_l + (uint32_t)(np * 16 * ROWB) + ko;
                uint32_t r[4];
                ldsm_x4(tb + GS_BH + off, r);
                bhf[2 * np][0] = r[0]; bhf[2 * np][1] = r[1];
                bhf[2 * np + 1][0] = r[2]; bhf[2 * np + 1][1] = r[3];
                ldsm_x4(tb + GS_BL + off, r);
                blf[2 * np][0] = r[0]; blf[2 * np][1] = r[1];
                blf[2 * np + 1][0] = r[2]; blf[2 * np + 1][1] = r[3];
            }
#pragma unroll
            for (int mt = 0; mt < 2; mt++) {
#pragma unroll
                for (int nt = 0; nt < 8; nt++) {
                    mma_bf16(acc[mt][nt], ah[mt], bhf[nt]);
                    mma_bf16(acc[mt][nt], ah[mt], blf[nt]);
                    mma_bf16(acc[mt][nt], al[mt], bhf[nt]);
                }
            }
        }
    }

    // Epilogue: split fp32 accumulators into bf16 hi/lo pairs
    const int r0 = rowA + warpM * 32 + (lane >> 2);
    const int c0 = colB + warpN * 64 + (lane & 3) * 2;
#pragma unroll
    for (int mt = 0; mt < 2; mt++) {
#pragma unroll
        for (int nt = 0; nt < 8; nt++) {
            int rr = r0 + mt * 16;
            int cc = c0 + nt * 8;
#pragma unroll
            for (int h = 0; h < 2; h++) {
                float a = acc[mt][nt][2 * h + 0];
                float b = acc[mt][nt][2 * h + 1];
                size_t idx = (size_t)(rr + 8 * h) * HID + cc;
                __nv_bfloat16 ha = __float2bfloat16_rn(a);
                __nv_bfloat16 hb = __float2bfloat16_rn(b);
                __nv_bfloat16 la = __float2bfloat16_rn(a - __bfloat162float(ha));
                __nv_bfloat16 lb = __float2bfloat16_rn(b - __bfloat162float(hb));
                __nv_bfloat162 hp(ha, hb), lp(la, lb);
                *(uint32_t*)(Qh + idx) = *(uint32_t*)&hp;
                *(uint32_t*)(Ql + idx) = *(uint32_t*)&lp;
            }
        }
    }
}

// ---------------------------------------------------------------------------
// Kernel 2: banded attention — EXACT R10/R13 body (dense QK, band-aware PV)
// ---------------------------------------------------------------------------
#define TQ 64
#define TK 192
#define SW2 200
#define PSTR 216

#define A3_QSTG 40960
#define A3_S    0
#define A3_PH   55296
#define A3_PL   82944
#define A3_V    0
#define A3_SMEM 110592

__global__ __launch_bounds__(256, 2)
void attn_hmma_kernel(const __nv_bfloat16* __restrict__ Qh,
                      const __nv_bfloat16* __restrict__ Ql,
                      const __nv_bfloat16* __restrict__ Kh,
                      const __nv_bfloat16* __restrict__ Kl,
                      const float* __restrict__ repr,
                      float* __restrict__ out)
{
    extern __shared__ char dynsm[];
    const uint32_t sbase = smem_u32(dynsm);
    float* S = (float*)(dynsm + A3_S);

    const int b   = blockIdx.y;
    const int q0  = blockIdx.x * TQ;
    const int k0  = q0 - WSIZE;
    const int tid = threadIdx.x;
    const int wid = tid >> 5;
    const int lane = tid & 31;
    const int warpM = wid >> 2;
    const int warpN = wid & 3;

    const size_t bOfs = (size_t)b * SEQ * HID;
    const float* reB = repr + bOfs;
    float*       oB  = out  + bOfs;

    // ---------------- Phase 1: S = Q' K^T (split bf16 HMMA) ---------------
    {
        auto load_qk = [&](int c, int stage) {
            const int ko = c * 32;
            const uint32_t tb = sbase + stage * A3_QSTG;
            {
                int r = tid >> 2, cc = tid & 3;
                uint32_t d = (uint32_t)(r * 80 + cc * 16);
                cp16(tb + 0    + d, Qh + bOfs + (size_t)(q0 + r) * HID + ko + cc * 8);
                cp16(tb + 5120 + d, Ql + bOfs + (size_t)(q0 + r) * HID + ko + cc * 8);
            }
#pragma unroll
            for (int i = 0; i < 3; i++) {
                int e = tid + i * 256;
                int r = e >> 2, cc = e & 3;
                int j = k0 + r;
                uint32_t d = (uint32_t)(r * 80 + cc * 16);
                if (j >= 0 && j < SEQ) {
                    cp16(tb + 10240 + d, Kh + bOfs + (size_t)j * HID + ko + cc * 8);
                    cp16(tb + 25600 + d, Kl + bOfs + (size_t)j * HID + ko + cc * 8);
                } else {
                    zero16(tb + 10240 + d);
                    zero16(tb + 25600 + d);
                }
            }
            CP_COMMIT();
        };

        float acc[2][6][4];
#pragma unroll
        for (int mt = 0; mt < 2; mt++)
#pragma unroll
            for (int nt = 0; nt < 6; nt++)
#pragma unroll
                for (int q = 0; q < 4; q++) acc[mt][nt][q] = 0.f;

        load_qk(0, 0);
        for (int c = 0; c < 32; c++) {
            if (c + 1 < 32) { load_qk(c + 1, (c + 1) & 1); CP_WAIT(1); }
            else            { CP_WAIT(0); }
            __syncthreads();

            const uint32_t tb = sbase + (c & 1) * A3_QSTG;
            const uint32_t a_l = (uint32_t)((warpM * 32 + (lane & 15)) * 80 + (lane >> 4) * 16);
            const int g = lane >> 3;
            const uint32_t b_l = (uint32_t)((warpN * 48 + ((g >> 1) << 3) + (lane & 7)) * 80 + (g & 1) * 16);

#pragma unroll
            for (int kk = 0; kk < 2; kk++) {
                const uint32_t ko = (uint32_t)(kk * 32);
                uint32_t aqh[2][4], aql[2][4], bkh[6][2], bkl[6][2];
#pragma unroll
                for (int mt = 0; mt < 2; mt++) {
                    uint32_t off = a_l + (uint32_t)(mt * 16 * 80) + ko;
                    ldsm_x4(tb + 0    + off, aqh[mt]);
                    ldsm_x4(tb + 5120 + off, aql[mt]);
                }
#pragma unroll
                for (int np = 0; np < 3; np++) {
                    uint32_t off = b_l + (uint32_t)(np * 16 * 80) + ko;
                    uint32_t r[4];
                    ldsm_x4(tb + 10240 + off, r);
                    bkh[2 * np][0] = r[0]; bkh[2 * np][1] = r[1];
                    bkh[2 * np + 1][0] = r[2]; bkh[2 * np + 1][1] = r[3];
                    ldsm_x4(tb + 25600 + off, r);
                    bkl[2 * np][0] = r[0]; bkl[2 * np][1] = r[1];
                    bkl[2 * np + 1][0] = r[2]; bkl[2 * np + 1][1] = r[3];
                }
#pragma unroll
                for (int mt = 0; mt < 2; mt++)
#pragma unroll
                    for (int nt = 0; nt < 6; nt++) {
                        mma_bf16(acc[mt][nt], aqh[mt], bkh[nt]);
                        mma_bf16(acc[mt][nt], aqh[mt], bkl[nt]);
                        mma_bf16(acc[mt][nt], aql[mt], bkh[nt]);
                    }
            }
            __syncthreads();
        }

        __syncthreads();

        const int r0 = warpM * 32 + (lane >> 2);
        const int c0 = warpN * 48 + (lane & 3) * 2;
#pragma unroll
        for (int mt = 0; mt < 2; mt++)
#pragma unroll
            for (int nt = 0; nt < 6; nt++) {
                *(float2*)&S[(r0 + mt * 16) * SW2 + c0 + nt * 8] =
                    make_float2(acc[mt][nt][0], acc[mt][nt][1]);
                *(float2*)&S[(r0 + mt * 16 + 8) * SW2 + c0 + nt * 8] =
                    make_float2(acc[mt][nt][2], acc[mt][nt][3]);
            }
        __syncthreads();
    }

    // ---------------- Phase 2: masked softmax + P split to bf16 ------------
    {
        __nv_bfloat16* ph = (__nv_bfloat16*)(dynsm + A3_PH);
        __nv_bfloat16* pl = (__nv_bfloat16*)(dynsm + A3_PL);
        const int row  = tid >> 2;
        const int quad = tid & 3;
        const int cbeg = quad * 48;
        const int i_gl = q0 + row;

        float mx = -3.4e38f;
#pragma unroll 8
        for (int c = cbeg; c < cbeg + 48; c++) {
            int j = k0 + c;
            int d = i_gl - j;
            bool valid = (j >= 0) && (j < SEQ) && (d <= WSIZE) && (d >= -WSIZE);
            float v = valid ? S[row * SW2 + c] : NEG_INF;
            S[row * SW2 + c] = v;
            mx = fmaxf(mx, v);
        }
        mx = fmaxf(mx, __shfl_xor_sync(0xffffffffu, mx, 1));
        mx = fmaxf(mx, __shfl_xor_sync(0xffffffffu, mx, 2));

        float sum = 0.f;
#pragma unroll 8
        for (int c = cbeg; c < cbeg + 48; c++) {
            float e = __expf(S[row * SW2 + c] - mx);
            S[row * SW2 + c] = e;
            sum += e;
        }
        sum += __shfl_xor_sync(0xffffffffu, sum, 1);
        sum += __shfl_xor_sync(0xffffffffu, sum, 2);
        float inv = 1.f / sum;
#pragma unroll 8
        for (int c = cbeg; c < cbeg + 48; c++) {
            float p = S[row * SW2 + c] * inv;
            __nv_bfloat16 hp = __float2bfloat16_rn(p);
            __nv_bfloat16 lp = __float2bfloat16_rn(p - __bfloat162float(hp));
            ph[row * PSTR + c] = hp;
            pl[row * PSTR + c] = lp;
        }
    }
    __syncthreads();

    // ---------------- Phase 3: out = repr + relu(P @ V), band-aware --------
    {
        auto load_v = [&](int ch) {
            const int d0 = ch * 64;
            const uint32_t tb = sbase + A3_V;
#pragma unroll
            for (int i = 0; i < 6; i++) {
                int e = tid + i * 256;
                int r = e >> 3, cc = e & 7;
                int j = k0 + r;
                uint32_t d = (uint32_t)(r * 144 + cc * 16);
                if (j >= 0 && j < SEQ) {
                    cp16(tb + d,         Kh + bOfs + (size_t)j * HID + d0 + cc * 8);
                    cp16(tb + 27648 + d, Kl + bOfs + (size_t)j * HID + d0 + cc * 8);
                } else {
                    zero16(tb + d);
                    zero16(tb + 27648 + d);
                }
            }
            CP_COMMIT();
        };

        const uint32_t a_l = (uint32_t)((warpM * 32 + (lane & 15)) * (PSTR * 2) + (lane >> 4) * 16);
        const int g = lane >> 3;
        const int base0 = warpM * 2;

        for (int ch = 0; ch < 16; ch++) {
            load_v(ch);
            CP_WAIT(0);
            __syncthreads();

            const uint32_t vb = sbase + A3_V;
            float acc[2][2][4];
#pragma unroll
            for (int mt = 0; mt < 2; mt++)
#pragma unroll
                for (int nt = 0; nt < 2; nt++)
#pragma unroll
                    for (int q = 0; q < 4; q++) acc[mt][nt][q] = 0.f;

#pragma unroll
            for (int kq = 0; kq < 10; kq++) {
                const int ks = base0 + kq;
                uint32_t vaddr = (uint32_t)((ks * 16 + (g & 1) * 8 + (lane & 7)) * 144
                                            + (warpN * 16 + (g >> 1) * 8) * 2);
                uint32_t bvh[4], bvl[4];
                ldsm_x4_t(vb + vaddr, bvh);
                ldsm_x4_t(vb + 27648 + vaddr, bvl);

                if (kq < 9) {
                    uint32_t aph[4], apl[4];
                    uint32_t off = a_l + (uint32_t)(ks * 32);
                    ldsm_x4(sbase + A3_PH + off, aph);
                    ldsm_x4(sbase + A3_PL + off, apl);
#pragma unroll
                    for (int nt = 0; nt < 2; nt++) {
                        mma_bf16(acc[0][nt], aph, &bvh[nt * 2]);
                        mma_bf16(acc[0][nt], aph, &bvl[nt * 2]);
                        mma_bf16(acc[0][nt], apl, &bvh[nt * 2]);
                    }
                }
                if (kq > 0) {
                    uint32_t aph[4], apl[4];
                    uint32_t off = a_l + (uint32_t)(16 * (PSTR * 2)) + (uint32_t)(ks * 32);
                    ldsm_x4(sbase + A3_PH + off, aph);
                    ldsm_x4(sbase + A3_PL + off, apl);
#pragma unroll
                    for (int nt = 0; nt < 2; nt++) {
                        mma_bf16(acc[1][nt], aph, &bvh[nt * 2]);
                        mma_bf16(acc[1][nt], aph, &bvl[nt * 2]);
                        mma_bf16(acc[1][nt], apl, &bvh[nt * 2]);
                    }
                }
            }

            const int rq = q0 + warpM * 32 + (lane >> 2);
            const int cc0 = ch * 64 + warpN * 16 + (lane & 3) * 2;
#pragma unroll
            for (int mt = 0; mt < 2; mt++)
#pragma unroll
                for (int nt = 0; nt < 2; nt++) {
                    int rr = rq + mt * 16;
                    int cc = cc0 + nt * 8;
#pragma unroll
                    for (int h = 0; h < 2; h++) {
                        size_t idx = (size_t)(rr + 8 * h) * HID + cc;
                        float2 rv = *(const float2*)(reB + idx);
                        float2 ov = make_float2(rv.x + fmaxf(acc[mt][nt][2 * h], 0.f),
                                                rv.y + fmaxf(acc[mt][nt][2 * h + 1], 0.f));
                        *(float2*)(oB + idx) = ov;
                    }
                }
            __syncthreads();
        }
    }
}

// ---------------------------------------------------------------------------
// Launch (single stream, serial — overlap empirically falsified in R12/R15)
// ---------------------------------------------------------------------------
extern "C" void kernel_launch(void* const* d_in, const int* in_sizes, int n_in,
                              void* d_out, int out_size)
{
    const float* repr = (const float*)d_in[0];   // [8, 2048, 1024]
    const float* W    = (const float*)d_in[1];   // [1024, 1024]
    float* out        = (float*)d_out;

    __nv_bfloat16 *ah, *al, *qh, *ql, *bh, *bl;
    cudaGetSymbolAddress((void**)&ah, g_ah);
    cudaGetSymbolAddress((void**)&al, g_al);
    cudaGetSymbolAddress((void**)&qh, g_qh);
    cudaGetSymbolAddress((void**)&ql, g_ql);
    cudaGetSymbolAddress((void**)&bh, g_bh);
    cudaGetSymbolAddress((void**)&bl, g_bl);

    // 1) bf16 splits
    split_repr_kernel<<<(BATCH * SEQ * HID) / (256 * 4), 256>>>(repr, ah, al);
    wsplit_kernel<<<(HID / 32) * (HID / 32), 256>>>(W, bh, bl);

    // 2) HMMA split-bf16 GEMM (single-sync pipeline)
    {
        const int dyn = 2 * GS_SZ;   // 81920
        cudaFuncSetAttribute(gemm_hmma_kernel,
                             cudaFuncAttributeMaxDynamicSharedMemorySize, dyn);
        dim3 grid(HID / GBN, (BATCH * SEQ) / GBM);   // (8, 128)
        gemm_hmma_kernel<<<grid, 256, dyn>>>(ah, al, bh, bl, qh, ql);
    }

    // 3) HMMA banded attention (exact R10/R13 body)
    {
        cudaFuncSetAttribute(attn_hmma_kernel,
                             cudaFuncAttributeMaxDynamicSharedMemorySize, A3_SMEM);
        dim3 grid(SEQ / TQ, BATCH);                  // (32, 8)
        attn_hmma_kernel<<<grid, 256, A3_SMEM>>>(qh, ql, ah, al, repr, out);
    }
}